// round 9
// baseline (speedup 1.0000x reference)
#include <cuda_runtime.h>
#include <cuda_bf16.h>
#include <cuda_fp16.h>
#include <cstdint>

#define Nn 50000
#define Ne 800000
#define Rr 2000
#define Fd 128
#define FDh 384
#define Pp 64
#define EPSV 1e-12f
#define SRES 200  // resident SA3 smem row stride (halves): 192 + 8 pad

// fused kernel smem: SAr 128*200*2 + As 2*16384 + Bs 2*8192
#define SMEM_FUSED (128 * SRES * 2 + 2 * 16384 + 2 * 8192)

// ---------------- static scratch ----------------
__device__ int g_cnt[Nn];
__device__ int g_off[Nn + 1];
__device__ int g_ssrc[Ne];
__device__ int g_srel[Ne];
__device__ float g_arel[4 * Rr];
__device__ float g_M[4 * Nn];
__device__ float g_Z[4 * Nn];
__device__ float g_rnorm[2 * Nn];
__device__ float g_out[2][Nn * FDh];
__device__ __align__(16) __half g_entH[Nn * Fd];
__device__ __align__(16) __half g_relH[Rr * Fd];
__device__ __align__(16) __half g_rnH[Rr * Fd];
__device__ __align__(16) __half g_fh0[2][Nn * Fd];
__device__ __align__(16) __half g_fh1[2][Nn * Fd];
__device__ __align__(16) __nv_bfloat16 g_gateT[2][FDh * FDh];
__device__ __align__(16) __nv_bfloat16 g_proxyN[2][Pp * FDh];
__device__ __align__(16) __nv_bfloat16 g_PGtn[2][FDh * Pp];
__device__ __align__(16) __nv_bfloat16 g_PB3[2][FDh * 192];
__device__ __align__(16) __nv_bfloat16 g_ob[2][Nn * FDh];

// ---------------- helpers ----------------
__device__ __forceinline__ float wredsum(float v) {
#pragma unroll
    for (int o = 16; o; o >>= 1) v += __shfl_xor_sync(0xffffffffu, v, o);
    return v;
}
__device__ __forceinline__ float wredmax(float v) {
#pragma unroll
    for (int o = 16; o; o >>= 1) v = fmaxf(v, __shfl_xor_sync(0xffffffffu, v, o));
    return v;
}

__device__ __forceinline__ int swz(int r, int c) {  // halves; c multiple of 8
    return r * 64 + (c ^ ((r & 7) << 3));
}

__device__ __forceinline__ void ldm4(unsigned* r, const void* p) {
    unsigned a = (unsigned)__cvta_generic_to_shared(p);
    asm volatile("ldmatrix.sync.aligned.m8n8.x4.shared.b16 {%0,%1,%2,%3},[%4];"
                 : "=r"(r[0]), "=r"(r[1]), "=r"(r[2]), "=r"(r[3]) : "r"(a));
}

__device__ __forceinline__ void mma16816(float* c, unsigned a0, unsigned a1,
                                         unsigned a2, unsigned a3,
                                         unsigned b0, unsigned b1) {
    asm volatile(
        "mma.sync.aligned.m16n8k16.row.col.f32.bf16.bf16.f32 "
        "{%0,%1,%2,%3},{%4,%5,%6,%7},{%8,%9},{%0,%1,%2,%3};\n"
        : "+f"(c[0]), "+f"(c[1]), "+f"(c[2]), "+f"(c[3])
        : "r"(a0), "r"(a1), "r"(a2), "r"(a3), "r"(b0), "r"(b1));
}

__device__ __forceinline__ void cpa16(__nv_bfloat16* dst, const void* src, bool pred) {
    unsigned d = (unsigned)__cvta_generic_to_shared(dst);
    int sz = pred ? 16 : 0;
    asm volatile("cp.async.cg.shared.global [%0], [%1], 16, %2;" :: "r"(d), "l"(src), "r"(sz));
}

__device__ __forceinline__ uint2 pack4bf(float4 v) {
    __nv_bfloat162 p0 = __floats2bfloat162_rn(v.x, v.y);
    __nv_bfloat162 p1 = __floats2bfloat162_rn(v.z, v.w);
    return make_uint2(*(unsigned*)&p0, *(unsigned*)&p1);
}
__device__ __forceinline__ uint2 pack4h(float4 v) {
    __half2 h0 = __floats2half2_rn(v.x, v.y);
    __half2 h1 = __floats2half2_rn(v.z, v.w);
    return make_uint2(*(unsigned*)&h0, *(unsigned*)&h1);
}

// ===== GEMM machinery (swizzled, streamed, double-buffered) =====
__device__ __forceinline__ void loadA_a(__nv_bfloat16* As, const __nv_bfloat16* A,
                                        int row0, int lda, int kt, int t, int rowmax) {
#pragma unroll
    for (int i = 0; i < 4; i++) {
        int idx = t + i * 256;
        int r = idx >> 3, c = (idx & 7) * 8;
        int gr = row0 + r;
        int cr = gr < rowmax ? gr : rowmax - 1;
        cpa16(As + swz(r, c), A + (size_t)cr * lda + kt + c, gr < rowmax);
    }
}
__device__ __forceinline__ void loadB_a(__nv_bfloat16* Bs, const __nv_bfloat16* B,
                                        int col0, int ldb, int kt, int t) {
#pragma unroll
    for (int i = 0; i < 2; i++) {
        int idx = t + i * 256;
        int r = idx >> 3, c = (idx & 7) * 8;
        cpa16(Bs + swz(r, c), B + (size_t)(col0 + r) * ldb + kt + c, true);
    }
}
__device__ __forceinline__ void mmastep64(float (&acc)[2][4][4], const __nv_bfloat16* As,
                                          const __nv_bfloat16* Bs, int wm, int wn, int lane) {
    int lr = lane & 15, lc = (lane >> 4) * 8;
#pragma unroll
    for (int kk = 0; kk < 64; kk += 16) {
        unsigned ra[2][4], rb[2][4];
        ldm4(ra[0], As + swz(wm * 32 + lr, kk + lc));
        ldm4(ra[1], As + swz(wm * 32 + 16 + lr, kk + lc));
        ldm4(rb[0], Bs + swz(wn * 32 + lr, kk + lc));
        ldm4(rb[1], Bs + swz(wn * 32 + 16 + lr, kk + lc));
#pragma unroll
        for (int mt = 0; mt < 2; mt++) {
            mma16816(acc[mt][0], ra[mt][0], ra[mt][1], ra[mt][2], ra[mt][3], rb[0][0], rb[0][2]);
            mma16816(acc[mt][1], ra[mt][0], ra[mt][1], ra[mt][2], ra[mt][3], rb[0][1], rb[0][3]);
            mma16816(acc[mt][2], ra[mt][0], ra[mt][1], ra[mt][2], ra[mt][3], rb[1][0], rb[1][2]);
            mma16816(acc[mt][3], ra[mt][0], ra[mt][1], ra[mt][2], ra[mt][3], rb[1][1], rb[1][3]);
        }
    }
}
__device__ __forceinline__ void gemm_phase(float (&acc)[2][4][4],
                                           const __nv_bfloat16* A, int lda, int row0, int rowmax,
                                           const __nv_bfloat16* B, int ldb, int col0, int Ktot,
                                           __nv_bfloat16* As0, __nv_bfloat16* As1,
                                           __nv_bfloat16* Bs0, __nv_bfloat16* Bs1,
                                           int t, int wm, int wn, int lane) {
    int nt = Ktot >> 6;
    __nv_bfloat16* Ab[2] = {As0, As1};
    __nv_bfloat16* Bb[2] = {Bs0, Bs1};
    loadA_a(Ab[0], A, row0, lda, 0, t, rowmax);
    loadB_a(Bb[0], B, col0, ldb, 0, t);
    asm volatile("cp.async.commit_group;");
    for (int k = 0; k < nt; k++) {
        if (k + 1 < nt) {
            loadA_a(Ab[(k + 1) & 1], A, row0, lda, (k + 1) << 6, t, rowmax);
            loadB_a(Bb[(k + 1) & 1], B, col0, ldb, (k + 1) << 6, t);
            asm volatile("cp.async.commit_group;");
            asm volatile("cp.async.wait_group 1;");
        } else {
            asm volatile("cp.async.wait_group 0;");
        }
        __syncthreads();
        mmastep64(acc, Ab[k & 1], Bb[k & 1], wm, wn, lane);
        __syncthreads();
    }
}

// resident-A (SAr, stride SRES) + streamed swizzled B
__device__ __forceinline__ void mmares(float (&acc)[2][4][4], const __nv_bfloat16* Ares,
                                       int kt, const __nv_bfloat16* Bs,
                                       int wm, int wn, int lane) {
    int lr = lane & 15, lc = (lane >> 4) * 8;
#pragma unroll
    for (int kk = 0; kk < 64; kk += 16) {
        unsigned ra[2][4], rb[2][4];
        ldm4(ra[0], Ares + (wm * 32 + lr) * SRES + kt + kk + lc);
        ldm4(ra[1], Ares + (wm * 32 + 16 + lr) * SRES + kt + kk + lc);
        ldm4(rb[0], Bs + swz(wn * 32 + lr, kk + lc));
        ldm4(rb[1], Bs + swz(wn * 32 + 16 + lr, kk + lc));
#pragma unroll
        for (int mt = 0; mt < 2; mt++) {
            mma16816(acc[mt][0], ra[mt][0], ra[mt][1], ra[mt][2], ra[mt][3], rb[0][0], rb[0][2]);
            mma16816(acc[mt][1], ra[mt][0], ra[mt][1], ra[mt][2], ra[mt][3], rb[0][1], rb[0][3]);
            mma16816(acc[mt][2], ra[mt][0], ra[mt][1], ra[mt][2], ra[mt][3], rb[1][0], rb[1][2]);
            mma16816(acc[mt][3], ra[mt][0], ra[mt][1], ra[mt][2], ra[mt][3], rb[1][1], rb[1][3]);
        }
    }
}
__device__ __forceinline__ void bphase_res(float (&acc)[2][4][4], const __nv_bfloat16* Ares,
                                           const __nv_bfloat16* B, int ldb, int col0, int Ktot,
                                           __nv_bfloat16* Bs0, __nv_bfloat16* Bs1,
                                           int t, int wm, int wn, int lane) {
    int nt = Ktot >> 6;
    __nv_bfloat16* Bb[2] = {Bs0, Bs1};
    loadB_a(Bb[0], B, col0, ldb, 0, t);
    asm volatile("cp.async.commit_group;");
    for (int k = 0; k < nt; k++) {
        if (k + 1 < nt) {
            loadB_a(Bb[(k + 1) & 1], B, col0, ldb, (k + 1) << 6, t);
            asm volatile("cp.async.commit_group;");
            asm volatile("cp.async.wait_group 1;");
        } else {
            asm volatile("cp.async.wait_group 0;");
        }
        __syncthreads();
        mmares(acc, Ares, k << 6, Bb[k & 1], wm, wn, lane);
        __syncthreads();
    }
}

// ---------------- CSR build ----------------
__global__ void k_zero() {
    int i = blockIdx.x * blockDim.x + threadIdx.x;
    if (i < Nn) g_cnt[i] = 0;
}
__global__ void k_count(const int* __restrict__ dst) {
    int e = blockIdx.x * blockDim.x + threadIdx.x;
    if (e < Ne) atomicAdd(&g_cnt[dst[e]], 1);
}
__global__ void k_scan() {
    __shared__ int wsum[32];
    __shared__ int carry;
    int t = threadIdx.x, lane = t & 31, wid = t >> 5;
    if (t == 0) { carry = 0; g_off[0] = 0; }
    __syncthreads();
    for (int base = 0; base < Nn; base += 1024) {
        int i = base + t;
        int v = (i < Nn) ? g_cnt[i] : 0;
        if (i < Nn) g_cnt[i] = 0;
        int x = v;
#pragma unroll
        for (int o = 1; o < 32; o <<= 1) {
            int y = __shfl_up_sync(0xffffffffu, x, o);
            if (lane >= o) x += y;
        }
        if (lane == 31) wsum[wid] = x;
        __syncthreads();
        if (wid == 0) {
            int s = wsum[lane];
#pragma unroll
            for (int o = 1; o < 32; o <<= 1) {
                int y = __shfl_up_sync(0xffffffffu, s, o);
                if (lane >= o) s += y;
            }
            wsum[lane] = s;
        }
        __syncthreads();
        int pre = (wid > 0) ? wsum[wid - 1] : 0;
        int inc = x + pre + carry;
        if (i < Nn) g_off[i + 1] = inc;
        __syncthreads();
        if (t == 1023) carry = inc;
        __syncthreads();
    }
}
__global__ void k_scatter(const int* __restrict__ src, const int* __restrict__ dst,
                          const int* __restrict__ rel) {
    int e = blockIdx.x * blockDim.x + threadIdx.x;
    if (e < Ne) {
        int d = dst[e];
        int p = g_off[d] + atomicAdd(&g_cnt[d], 1);
        g_ssrc[p] = src[e];
        g_srel[p] = rel[e];
    }
}

// ---------------- relation precompute ----------------
__global__ void k_relnorm(const float* __restrict__ rel, const float* __restrict__ ae,
                          const float* __restrict__ ar) {
    int r = blockIdx.x;
    int t = threadIdx.x;  // 128
    float v = rel[r * Fd + t];
    float s = wredsum(v * v);
    __shared__ float sm[4];
    __shared__ float sm4[4][4];
    if ((t & 31) == 0) sm[t >> 5] = s;
    __syncthreads();
    float tot = sm[0] + sm[1] + sm[2] + sm[3];
    float nv = v / fmaxf(sqrtf(tot), EPSV);
    g_rnH[r * Fd + t] = __float2half(nv);
    float d0 = wredsum(nv * ae[t]);
    float d1 = wredsum(nv * ae[Fd + t]);
    float d2 = wredsum(nv * ar[t]);
    float d3 = wredsum(nv * ar[Fd + t]);
    if ((t & 31) == 0) {
        sm4[0][t >> 5] = d0; sm4[1][t >> 5] = d1;
        sm4[2][t >> 5] = d2; sm4[3][t >> 5] = d3;
    }
    __syncthreads();
    if (t < 4) g_arel[t * Rr + r] = sm4[t][0] + sm4[t][1] + sm4[t][2] + sm4[t][3];
}

// ---------------- fp32 -> fp16 of inputs ----------------
__global__ void k_conv16(const float* __restrict__ ent, const float* __restrict__ rel) {
    int i = blockIdx.x * blockDim.x + threadIdx.x;
    int totE = Nn * Fd / 4, totR = Rr * Fd / 4;
    if (i < totE) {
        float4 v = *(const float4*)(ent + (size_t)i * 4);
        *(uint2*)&g_entH[(size_t)i * 4] = pack4h(v);
    } else if (i < totE + totR) {
        int j = i - totE;
        float4 v = *(const float4*)(rel + (size_t)j * 4);
        *(uint2*)&g_relH[(size_t)j * 4] = pack4h(v);
    }
}

// ---------------- init mean + softmax stats (one CSR pass) ----------------
__global__ void k_initstats() {
    int w = (blockIdx.x * blockDim.x + threadIdx.x) >> 5;
    int lane = threadIdx.x & 31;
    if (w >= Nn) return;
    int b = g_off[w], e = g_off[w + 1];
    float m0 = -1e30f, m1 = -1e30f, m2 = -1e30f, m3 = -1e30f;
    for (int i = b + lane; i < e; i += 32) {
        int r = g_srel[i];
        m0 = fmaxf(m0, g_arel[r]);
        m1 = fmaxf(m1, g_arel[Rr + r]);
        m2 = fmaxf(m2, g_arel[2 * Rr + r]);
        m3 = fmaxf(m3, g_arel[3 * Rr + r]);
    }
    m0 = wredmax(m0); m1 = wredmax(m1); m2 = wredmax(m2); m3 = wredmax(m3);
    float z0 = 0, z1 = 0, z2 = 0, z3 = 0;
    for (int i = b + lane; i < e; i += 32) {
        int r = g_srel[i];
        z0 += expf(g_arel[r] - m0);
        z1 += expf(g_arel[Rr + r] - m1);
        z2 += expf(g_arel[2 * Rr + r] - m2);
        z3 += expf(g_arel[3 * Rr + r] - m3);
    }
    z0 = wredsum(z0); z1 = wredsum(z1); z2 = wredsum(z2); z3 = wredsum(z3);
    if (lane == 0) {
        g_M[w] = m0; g_M[Nn + w] = m1; g_M[2 * Nn + w] = m2; g_M[3 * Nn + w] = m3;
        g_Z[w] = z0; g_Z[Nn + w] = z1; g_Z[2 * Nn + w] = z2; g_Z[3 * Nn + w] = z3;
    }
    float4 aE = make_float4(0.f, 0.f, 0.f, 0.f);
    float4 aR = make_float4(0.f, 0.f, 0.f, 0.f);
    for (int i = b; i < e; i++) {
        int s = g_ssrc[i], r = g_srel[i];
        uint2 ue = *(const uint2*)&g_entH[(size_t)s * Fd + lane * 4];
        uint2 ur = *(const uint2*)&g_relH[(size_t)r * Fd + lane * 4];
        float2 e0 = __half22float2(*(__half2*)&ue.x), e1 = __half22float2(*(__half2*)&ue.y);
        float2 r0 = __half22float2(*(__half2*)&ur.x), r1 = __half22float2(*(__half2*)&ur.y);
        aE.x += e0.x; aE.y += e0.y; aE.z += e1.x; aE.w += e1.y;
        aR.x += r0.x; aR.y += r0.y; aR.z += r1.x; aR.w += r1.y;
    }
    float inv = 1.f / fmaxf((float)(e - b), 1.f);
    float4 o0 = make_float4(tanhf(aE.x * inv), tanhf(aE.y * inv), tanhf(aE.z * inv), tanhf(aE.w * inv));
    float4 o1 = make_float4(tanhf(aR.x * inv), tanhf(aR.y * inv), tanhf(aR.z * inv), tanhf(aR.w * inv));
    int oidx = w * FDh + lane * 4;
    *(float4*)&g_out[0][oidx] = o0;
    *(float4*)&g_out[1][oidx] = o1;
    int hidx = w * Fd + lane * 4;
    *(uint2*)&g_fh0[0][hidx] = pack4h(o0);
    *(uint2*)&g_fh0[1][hidx] = pack4h(o1);
    *(uint2*)&g_ob[0][oidx] = pack4bf(o0);
    *(uint2*)&g_ob[1][oidx] = pack4bf(o1);
}

// ---------------- Householder + attention aggregation ----------------
__global__ void k_agg(int layer) {
    int w = (blockIdx.x * blockDim.x + threadIdx.x) >> 5;
    int lane = threadIdx.x & 31;
    if (w >= Nn) return;
    int b = g_off[w], e = g_off[w + 1];
    int oidx = w * FDh + (layer + 1) * Fd + lane * 4;
    int hidx = w * Fd + lane * 4;
    const __half* fsrc0 = layer == 0 ? g_fh0[0] : g_fh1[0];
    const __half* fsrc1 = layer == 0 ? g_fh0[1] : g_fh1[1];
    if (b == e) {
        float4 z = make_float4(0.f, 0.f, 0.f, 0.f);
        *(float4*)&g_out[0][oidx] = z;
        *(float4*)&g_out[1][oidx] = z;
        uint2 zu = make_uint2(0u, 0u);
        if (layer == 0) { *(uint2*)&g_fh1[0][hidx] = zu; *(uint2*)&g_fh1[1][hidx] = zu; }
        *(uint2*)&g_ob[0][oidx] = zu;
        *(uint2*)&g_ob[1][oidx] = zu;
        return;
    }
    int dl0 = layer, dl1 = 2 + layer;
    float M0 = g_M[dl0 * Nn + w], Zi0 = 1.f / g_Z[dl0 * Nn + w];
    float M1 = g_M[dl1 * Nn + w], Zi1 = 1.f / g_Z[dl1 * Nn + w];
    float4 a0 = make_float4(0.f, 0.f, 0.f, 0.f);
    float4 a1 = make_float4(0.f, 0.f, 0.f, 0.f);
    for (int i = b; i < e; i++) {
        int s = g_ssrc[i], r = g_srel[i];
        float w0 = expf(g_arel[dl0 * Rr + r] - M0) * Zi0;
        float w1 = expf(g_arel[dl1 * Rr + r] - M1) * Zi1;
        uint2 urv = *(const uint2*)&g_rnH[(size_t)r * Fd + lane * 4];
        uint2 uf0 = *(const uint2*)&fsrc0[(size_t)s * Fd + lane * 4];
        uint2 uf1 = *(const uint2*)&fsrc1[(size_t)s * Fd + lane * 4];
        float2 rva = __half22float2(*(__half2*)&urv.x), rvb = __half22float2(*(__half2*)&urv.y);
        float2 f0a = __half22float2(*(__half2*)&uf0.x), f0b = __half22float2(*(__half2*)&uf0.y);
        float2 f1a = __half22float2(*(__half2*)&uf1.x), f1b = __half22float2(*(__half2*)&uf1.y);
        float p0 = f0a.x * rva.x + f0a.y * rva.y + f0b.x * rvb.x + f0b.y * rvb.y;
        float p1 = f1a.x * rva.x + f1a.y * rva.y + f1b.x * rvb.x + f1b.y * rvb.y;
        p0 = wredsum(p0) * 2.f;
        p1 = wredsum(p1) * 2.f;
        a0.x += w0 * (f0a.x - p0 * rva.x); a0.y += w0 * (f0a.y - p0 * rva.y);
        a0.z += w0 * (f0b.x - p0 * rvb.x); a0.w += w0 * (f0b.y - p0 * rvb.y);
        a1.x += w1 * (f1a.x - p1 * rva.x); a1.y += w1 * (f1a.y - p1 * rva.y);
        a1.z += w1 * (f1b.x - p1 * rvb.x); a1.w += w1 * (f1b.y - p1 * rvb.y);
    }
    float4 o0 = make_float4(tanhf(a0.x), tanhf(a0.y), tanhf(a0.z), tanhf(a0.w));
    float4 o1 = make_float4(tanhf(a1.x), tanhf(a1.y), tanhf(a1.z), tanhf(a1.w));
    *(float4*)&g_out[0][oidx] = o0;
    *(float4*)&g_out[1][oidx] = o1;
    if (layer == 0) {
        *(uint2*)&g_fh1[0][hidx] = pack4h(o0);
        *(uint2*)&g_fh1[1][hidx] = pack4h(o1);
    }
    *(uint2*)&g_ob[0][oidx] = pack4bf(o0);
    *(uint2*)&g_ob[1][oidx] = pack4bf(o1);
}

// ---------------- epilogue prep ----------------
__global__ void k_prep_gate(const float* __restrict__ ge, const float* __restrict__ gr) {
    int n = blockIdx.x, dual = blockIdx.y, k = threadIdx.x;
    const float* g = dual ? gr : ge;
    g_gateT[dual][n * FDh + k] = __float2bfloat16(g[k * FDh + n]);
}
__global__ void k_prep_proxy(const float* __restrict__ pe, const float* __restrict__ pr) {
    int p = blockIdx.x, dual = blockIdx.y, f = threadIdx.x;  // 384 threads
    const float* P = dual ? pr : pe;
    float v = P[p * FDh + f];
    __shared__ float sm[12];
    float s = wredsum(v * v);
    if ((f & 31) == 0) sm[f >> 5] = s;
    __syncthreads();
    float tot = 0.f;
#pragma unroll
    for (int i = 0; i < 12; i++) tot += sm[i];
    float nv = v / fmaxf(sqrtf(tot), EPSV);
    g_proxyN[dual][p * FDh + f] = __float2bfloat16(nv);
    __nv_bfloat16 h = __float2bfloat16(v);
    __nv_bfloat16 l = __float2bfloat16(v - __bfloat162float(h));
    g_PB3[dual][f * 192 + p] = h;
    g_PB3[dual][f * 192 + 64 + p] = l;
    g_PB3[dual][f * 192 + 128 + p] = h;
}
__global__ void k_prep_pg(const float* __restrict__ pe, const float* __restrict__ pr,
                          const float* __restrict__ ge, const float* __restrict__ gr) {
    int f = blockIdx.x, dual = blockIdx.y, p = threadIdx.x;  // 64 threads
    const float* P = dual ? pr : pe;
    const float* g = dual ? gr : ge;
    float acc = 0.f;
    for (int k = 0; k < FDh; k++) acc += P[p * FDh + k] * g[k * FDh + f];
    g_PGtn[dual][f * Pp + p] = __float2bfloat16(-acc);
}

// ---------------- inverse row norms of ob ----------------
__global__ void k_rnorm() {
    int w = (blockIdx.x * blockDim.x + threadIdx.x) >> 5;
    int lane = threadIdx.x & 31;
    int dual = blockIdx.y;
    if (w >= Nn) return;
    const __nv_bfloat16* row = &g_ob[dual][(size_t)w * FDh];
    float s = 0.f;
#pragma unroll
    for (int k = 0; k < 3; k++) {
        uint2 u = *(const uint2*)&row[lane * 4 + k * 128];
        float2 a = __bfloat1622float2(*(__nv_bfloat162*)&u.x);
        float2 b = __bfloat1622float2(*(__nv_bfloat162*)&u.y);
        s += a.x * a.x + a.y * a.y + b.x * b.x + b.y * b.y;
    }
    s = wredsum(s);
    if (lane == 0) g_rnorm[dual * Nn + w] = 1.f / fmaxf(sqrtf(s), EPSV);
}

// ---------------- fused S+softmax+final ----------------
__global__ void __launch_bounds__(256) k_fused(const float* __restrict__ be,
                                               const float* __restrict__ br,
                                               float* __restrict__ out) {
    extern __shared__ __align__(16) char sbuf[];
    __nv_bfloat16* SAr = (__nv_bfloat16*)sbuf;       // 128 x SRES resident SA3
    __nv_bfloat16* As0 = SAr + 128 * SRES;
    __nv_bfloat16* As1 = As0 + 8192;
    __nv_bfloat16* Bs0 = As1 + 8192;
    __nv_bfloat16* Bs1 = Bs0 + 4096;
    float* Sf = (float*)As0;                          // 128x64 fp32 (32KB) reuses As
    int t = threadIdx.x, lane = t & 31, wid = t >> 5;
    int wm = wid >> 1, wn = wid & 1;
    int row0 = blockIdx.x * 128, dual = blockIdx.y;

    // ---- Phase S: raw = ob @ proxyN^T (K=384) ----
    float acc[2][4][4];
#pragma unroll
    for (int a = 0; a < 2; a++)
#pragma unroll
        for (int bq = 0; bq < 4; bq++)
#pragma unroll
            for (int c = 0; c < 4; c++) acc[a][bq][c] = 0.f;
    gemm_phase(acc, g_ob[dual], 384, row0, Nn, g_proxyN[dual], 384, 0, 384,
               As0, As1, Bs0, Bs1, t, wm, wn, lane);
#pragma unroll
    for (int mt = 0; mt < 2; mt++)
#pragma unroll
        for (int n8 = 0; n8 < 4; n8++) {
            int row = wm * 32 + mt * 16 + (lane >> 2);
            int col = wn * 32 + n8 * 8 + (lane & 3) * 2;
            Sf[row * 64 + col] = acc[mt][n8][0];
            Sf[row * 64 + col + 1] = acc[mt][n8][1];
            Sf[(row + 8) * 64 + col] = acc[mt][n8][2];
            Sf[(row + 8) * 64 + col + 1] = acc[mt][n8][3];
        }
    __syncthreads();

    // ---- softmax rows (scaled by inverse ob-row norm) -> SAr (hi|hi|lo) ----
    for (int rr = 0; rr < 16; rr++) {
        int row = wid * 16 + rr;
        int gn = row0 + row;
        float r0 = 0.f, r1 = 0.f;
        if (gn < Nn) {
            float inv = g_rnorm[dual * Nn + gn];
            float v0 = Sf[row * 64 + lane] * inv, v1 = Sf[row * 64 + 32 + lane] * inv;
            float m = wredmax(fmaxf(v0, v1));
            float e0 = expf(v0 - m), e1 = expf(v1 - m);
            float s = wredsum(e0 + e1);
            r0 = e0 / s; r1 = e1 / s;
        }
        __nv_bfloat16 h0 = __float2bfloat16(r0), h1 = __float2bfloat16(r1);
        __nv_bfloat16 l0 = __float2bfloat16(r0 - __bfloat162float(h0));
        __nv_bfloat16 l1 = __float2bfloat16(r1 - __bfloat162float(h1));
        __nv_bfloat16* dstp = &SAr[row * SRES];
        dstp[lane] = h0; dstp[32 + lane] = h1;
        dstp[64 + lane] = h0; dstp[96 + lane] = h1;
        dstp[128 + lane] = l0; dstp[160 + lane] = l1;
    }
    __syncthreads();

    // ---- col-tile loop: Z + correction + SAP, epilogue ----
    const float* bias = dual ? br : be;
    for (int ct = 0; ct < 6; ct++) {
        int col0 = ct * 64;
        float accZ[2][4][4], accS[2][4][4];
#pragma unroll
        for (int a = 0; a < 2; a++)
#pragma unroll
            for (int bq = 0; bq < 4; bq++)
#pragma unroll
                for (int c = 0; c < 4; c++) { accZ[a][bq][c] = 0.f; accS[a][bq][c] = 0.f; }
        gemm_phase(accZ, g_ob[dual], 384, row0, Nn, g_gateT[dual], 384, col0, 384,
                   As0, As1, Bs0, Bs1, t, wm, wn, lane);
        bphase_res(accZ, SAr, g_PGtn[dual], Pp, col0, 64, Bs0, Bs1, t, wm, wn, lane);
        bphase_res(accS, SAr, g_PB3[dual], 192, col0, 192, Bs0, Bs1, t, wm, wn, lane);
#pragma unroll
        for (int mt = 0; mt < 2; mt++)
#pragma unroll
            for (int n8 = 0; n8 < 4; n8++) {
                int rbase = wm * 32 + mt * 16 + (lane >> 2);
                int gc = col0 + wn * 32 + n8 * 8 + (lane & 3) * 2;
                float b0 = bias[gc], b1 = bias[gc + 1];
#pragma unroll
                for (int h = 0; h < 2; h++) {
                    int gr = row0 + rbase + h * 8;
                    if (gr < Nn) {
                        float z0 = accZ[mt][n8][h * 2], z1 = accZ[mt][n8][h * 2 + 1];
                        float s0 = accS[mt][n8][h * 2], s1 = accS[mt][n8][h * 2 + 1];
                        float2 ov = *(const float2*)&g_out[dual][(size_t)gr * FDh + gc];
                        float gt0 = 1.f / (1.f + expf(-(z0 + b0)));
                        float gt1 = 1.f / (1.f + expf(-(z1 + b1)));
                        float o0 = ov.x - (1.f - gt0) * s0;
                        float o1 = ov.y - (1.f - gt1) * s1;
                        *(float2*)&out[(size_t)gr * 768 + dual * 384 + gc] = make_float2(o0, o1);
                    }
                }
            }
        __syncthreads();
    }
}

// ---------------- launch ----------------
extern "C" void kernel_launch(void* const* d_in, const int* in_sizes, int n_in,
                              void* d_out, int out_size) {
    const float* ent = (const float*)d_in[0];
    const float* rel = (const float*)d_in[1];
    const int* esrc = (const int*)d_in[2];
    const int* edst = (const int*)d_in[3];
    const int* erel = (const int*)d_in[4];
    const float* attn_e = (const float*)d_in[5];
    const float* gate_e = (const float*)d_in[6];
    const float* proxy_e = (const float*)d_in[7];
    const float* bias_e = (const float*)d_in[8];
    const float* attn_r = (const float*)d_in[9];
    const float* gate_r = (const float*)d_in[10];
    const float* proxy_r = (const float*)d_in[11];
    const float* bias_r = (const float*)d_in[12];
    float* out = (float*)d_out;

    cudaFuncSetAttribute(k_fused, cudaFuncAttributeMaxDynamicSharedMemorySize, SMEM_FUSED);

    k_zero<<<(Nn + 255) / 256, 256>>>();
    k_count<<<(Ne + 255) / 256, 256>>>(edst);
    k_scan<<<1, 1024>>>();
    k_scatter<<<(Ne + 255) / 256, 256>>>(esrc, edst, erel);
    k_relnorm<<<Rr, 128>>>(rel, attn_e, attn_r);

    int convTot = (Nn + Rr) * Fd / 4;
    k_conv16<<<(convTot + 255) / 256, 256>>>(ent, rel);

    int wblocks = (Nn + 7) / 8;
    k_initstats<<<wblocks, 256>>>();
    k_agg<<<wblocks, 256>>>(0);
    k_agg<<<wblocks, 256>>>(1);

    k_prep_gate<<<dim3(FDh, 2), FDh>>>(gate_e, gate_r);
    k_prep_proxy<<<dim3(Pp, 2), FDh>>>(proxy_e, proxy_r);
    k_prep_pg<<<dim3(FDh, 2), Pp>>>(proxy_e, proxy_r, gate_e, gate_r);
    k_rnorm<<<dim3(wblocks, 2), 256>>>();

    int mblocks = (Nn + 127) / 128;
    k_fused<<<dim3(mblocks, 2), 256, SMEM_FUSED>>>(bias_e, bias_r, out);
}

// round 10
// speedup vs baseline: 1.3432x; 1.3432x over previous
#include <cuda_runtime.h>
#include <cuda_bf16.h>
#include <cuda_fp16.h>
#include <cstdint>

#define Nn 50000
#define Ne 800000
#define Rr 2000
#define Fd 128
#define FDh 384
#define Pp 64
#define EPSV 1e-12f

// ---------------- static scratch ----------------
__device__ int g_cnt[Nn];
__device__ int g_off[Nn + 1];
__device__ int g_ssrc[Ne];
__device__ int g_srel[Ne];
__device__ float4 g_arelE[Rr];          // exp(attention logit) for the 4 (dual,layer) combos
__device__ float g_Z[4 * Nn];
__device__ float g_rnorm[2 * Nn];
__device__ float g_out[2][Nn * FDh];
__device__ __align__(16) __half g_entH[Nn * Fd];
__device__ __align__(16) __half g_relH[Rr * Fd];
__device__ __align__(16) __half g_rnH[Rr * Fd];
__device__ __align__(16) __half g_fh0[2][Nn * Fd];
__device__ __align__(16) __half g_fh1[2][Nn * Fd];
__device__ __align__(16) __nv_bfloat16 g_gateT[2][FDh * FDh];
__device__ __align__(16) __nv_bfloat16 g_proxyN[2][Pp * FDh];
__device__ __align__(16) __nv_bfloat16 g_PGtn[2][FDh * Pp];
__device__ __align__(16) __nv_bfloat16 g_PB3[2][FDh * 192];
__device__ __align__(16) __nv_bfloat16 g_ob[2][Nn * FDh];
__device__ __align__(16) __nv_bfloat16 g_SA3[2][Nn * 192];

// ---------------- helpers ----------------
__device__ __forceinline__ float wredsum(float v) {
#pragma unroll
    for (int o = 16; o; o >>= 1) v += __shfl_xor_sync(0xffffffffu, v, o);
    return v;
}
__device__ __forceinline__ float wredmax(float v) {
#pragma unroll
    for (int o = 16; o; o >>= 1) v = fmaxf(v, __shfl_xor_sync(0xffffffffu, v, o));
    return v;
}

__device__ __forceinline__ int swz(int r, int c) {  // halves; c multiple of 8
    return r * 64 + (c ^ ((r & 7) << 3));
}

__device__ __forceinline__ void ldm4(unsigned* r, const void* p) {
    unsigned a = (unsigned)__cvta_generic_to_shared(p);
    asm volatile("ldmatrix.sync.aligned.m8n8.x4.shared.b16 {%0,%1,%2,%3},[%4];"
                 : "=r"(r[0]), "=r"(r[1]), "=r"(r[2]), "=r"(r[3]) : "r"(a));
}

__device__ __forceinline__ void mma16816(float* c, unsigned a0, unsigned a1,
                                         unsigned a2, unsigned a3,
                                         unsigned b0, unsigned b1) {
    asm volatile(
        "mma.sync.aligned.m16n8k16.row.col.f32.bf16.bf16.f32 "
        "{%0,%1,%2,%3},{%4,%5,%6,%7},{%8,%9},{%0,%1,%2,%3};\n"
        : "+f"(c[0]), "+f"(c[1]), "+f"(c[2]), "+f"(c[3])
        : "r"(a0), "r"(a1), "r"(a2), "r"(a3), "r"(b0), "r"(b1));
}

__device__ __forceinline__ void cpa16(__nv_bfloat16* dst, const void* src, bool pred) {
    unsigned d = (unsigned)__cvta_generic_to_shared(dst);
    int sz = pred ? 16 : 0;
    asm volatile("cp.async.cg.shared.global [%0], [%1], 16, %2;" :: "r"(d), "l"(src), "r"(sz));
}

__device__ __forceinline__ uint2 pack4bf(float4 v) {
    __nv_bfloat162 p0 = __floats2bfloat162_rn(v.x, v.y);
    __nv_bfloat162 p1 = __floats2bfloat162_rn(v.z, v.w);
    return make_uint2(*(unsigned*)&p0, *(unsigned*)&p1);
}
__device__ __forceinline__ uint2 pack4h(float4 v) {
    __half2 h0 = __floats2half2_rn(v.x, v.y);
    __half2 h1 = __floats2half2_rn(v.z, v.w);
    return make_uint2(*(unsigned*)&h0, *(unsigned*)&h1);
}

// ===== GEMM machinery (swizzled, streamed, double-buffered) =====
__device__ __forceinline__ void loadA_a(__nv_bfloat16* As, const __nv_bfloat16* A,
                                        int row0, int lda, int kt, int t, int rowmax) {
#pragma unroll
    for (int i = 0; i < 4; i++) {
        int idx = t + i * 256;
        int r = idx >> 3, c = (idx & 7) * 8;
        int gr = row0 + r;
        int cr = gr < rowmax ? gr : rowmax - 1;
        cpa16(As + swz(r, c), A + (size_t)cr * lda + kt + c, gr < rowmax);
    }
}
__device__ __forceinline__ void loadB_a(__nv_bfloat16* Bs, const __nv_bfloat16* B,
                                        int col0, int ldb, int kt, int t) {
#pragma unroll
    for (int i = 0; i < 2; i++) {
        int idx = t + i * 256;
        int r = idx >> 3, c = (idx & 7) * 8;
        cpa16(Bs + swz(r, c), B + (size_t)(col0 + r) * ldb + kt + c, true);
    }
}
__device__ __forceinline__ void mmastep64(float (&acc)[2][4][4], const __nv_bfloat16* As,
                                          const __nv_bfloat16* Bs, int wm, int wn, int lane) {
    int lr = lane & 15, lc = (lane >> 4) * 8;
#pragma unroll
    for (int kk = 0; kk < 64; kk += 16) {
        unsigned ra[2][4], rb[2][4];
        ldm4(ra[0], As + swz(wm * 32 + lr, kk + lc));
        ldm4(ra[1], As + swz(wm * 32 + 16 + lr, kk + lc));
        ldm4(rb[0], Bs + swz(wn * 32 + lr, kk + lc));
        ldm4(rb[1], Bs + swz(wn * 32 + 16 + lr, kk + lc));
#pragma unroll
        for (int mt = 0; mt < 2; mt++) {
            mma16816(acc[mt][0], ra[mt][0], ra[mt][1], ra[mt][2], ra[mt][3], rb[0][0], rb[0][2]);
            mma16816(acc[mt][1], ra[mt][0], ra[mt][1], ra[mt][2], ra[mt][3], rb[0][1], rb[0][3]);
            mma16816(acc[mt][2], ra[mt][0], ra[mt][1], ra[mt][2], ra[mt][3], rb[1][0], rb[1][2]);
            mma16816(acc[mt][3], ra[mt][0], ra[mt][1], ra[mt][2], ra[mt][3], rb[1][1], rb[1][3]);
        }
    }
}
__device__ __forceinline__ void gemm_phase(float (&acc)[2][4][4],
                                           const __nv_bfloat16* A, int lda, int row0, int rowmax,
                                           const __nv_bfloat16* B, int ldb, int col0, int Ktot,
                                           __nv_bfloat16* As0, __nv_bfloat16* As1,
                                           __nv_bfloat16* Bs0, __nv_bfloat16* Bs1,
                                           int t, int wm, int wn, int lane) {
    int nt = Ktot >> 6;
    __nv_bfloat16* Ab[2] = {As0, As1};
    __nv_bfloat16* Bb[2] = {Bs0, Bs1};
    loadA_a(Ab[0], A, row0, lda, 0, t, rowmax);
    loadB_a(Bb[0], B, col0, ldb, 0, t);
    asm volatile("cp.async.commit_group;");
    for (int k = 0; k < nt; k++) {
        if (k + 1 < nt) {
            loadA_a(Ab[(k + 1) & 1], A, row0, lda, (k + 1) << 6, t, rowmax);
            loadB_a(Bb[(k + 1) & 1], B, col0, ldb, (k + 1) << 6, t);
            asm volatile("cp.async.commit_group;");
            asm volatile("cp.async.wait_group 1;");
        } else {
            asm volatile("cp.async.wait_group 0;");
        }
        __syncthreads();
        mmastep64(acc, Ab[k & 1], Bb[k & 1], wm, wn, lane);
        __syncthreads();
    }
}

// ---------------- CSR build ----------------
__global__ void k_zero() {
    int i = blockIdx.x * blockDim.x + threadIdx.x;
    if (i < Nn) g_cnt[i] = 0;
}
__global__ void k_count(const int* __restrict__ dst) {
    int e = blockIdx.x * blockDim.x + threadIdx.x;
    if (e < Ne) atomicAdd(&g_cnt[dst[e]], 1);
}
__global__ void k_scan() {
    __shared__ int wsum[32];
    __shared__ int carry;
    int t = threadIdx.x, lane = t & 31, wid = t >> 5;
    if (t == 0) { carry = 0; g_off[0] = 0; }
    __syncthreads();
    for (int base = 0; base < Nn; base += 1024) {
        int i = base + t;
        int v = (i < Nn) ? g_cnt[i] : 0;
        if (i < Nn) g_cnt[i] = 0;
        int x = v;
#pragma unroll
        for (int o = 1; o < 32; o <<= 1) {
            int y = __shfl_up_sync(0xffffffffu, x, o);
            if (lane >= o) x += y;
        }
        if (lane == 31) wsum[wid] = x;
        __syncthreads();
        if (wid == 0) {
            int s = wsum[lane];
#pragma unroll
            for (int o = 1; o < 32; o <<= 1) {
                int y = __shfl_up_sync(0xffffffffu, s, o);
                if (lane >= o) s += y;
            }
            wsum[lane] = s;
        }
        __syncthreads();
        int pre = (wid > 0) ? wsum[wid - 1] : 0;
        int inc = x + pre + carry;
        if (i < Nn) g_off[i + 1] = inc;
        __syncthreads();
        if (t == 1023) carry = inc;
        __syncthreads();
    }
}
__global__ void k_scatter(const int* __restrict__ src, const int* __restrict__ dst,
                          const int* __restrict__ rel) {
    int e = blockIdx.x * blockDim.x + threadIdx.x;
    if (e < Ne) {
        int d = dst[e];
        int p = g_off[d] + atomicAdd(&g_cnt[d], 1);
        g_ssrc[p] = src[e];
        g_srel[p] = rel[e];
    }
}

// ---------------- relation precompute ----------------
__global__ void k_relnorm(const float* __restrict__ rel, const float* __restrict__ ae,
                          const float* __restrict__ ar) {
    int r = blockIdx.x;
    int t = threadIdx.x;  // 128
    float v = rel[r * Fd + t];
    float s = wredsum(v * v);
    __shared__ float sm[4];
    __shared__ float sm4[4][4];
    if ((t & 31) == 0) sm[t >> 5] = s;
    __syncthreads();
    float tot = sm[0] + sm[1] + sm[2] + sm[3];
    float nv = v / fmaxf(sqrtf(tot), EPSV);
    g_rnH[r * Fd + t] = __float2half(nv);
    float d0 = wredsum(nv * ae[t]);
    float d1 = wredsum(nv * ae[Fd + t]);
    float d2 = wredsum(nv * ar[t]);
    float d3 = wredsum(nv * ar[Fd + t]);
    if ((t & 31) == 0) {
        sm4[0][t >> 5] = d0; sm4[1][t >> 5] = d1;
        sm4[2][t >> 5] = d2; sm4[3][t >> 5] = d3;
    }
    __syncthreads();
    if (t == 0) {
        float4 E;
        E.x = expf(sm4[0][0] + sm4[0][1] + sm4[0][2] + sm4[0][3]);
        E.y = expf(sm4[1][0] + sm4[1][1] + sm4[1][2] + sm4[1][3]);
        E.z = expf(sm4[2][0] + sm4[2][1] + sm4[2][2] + sm4[2][3]);
        E.w = expf(sm4[3][0] + sm4[3][1] + sm4[3][2] + sm4[3][3]);
        g_arelE[r] = E;
    }
}

// ---------------- fp32 -> fp16 of inputs ----------------
__global__ void k_conv16(const float* __restrict__ ent, const float* __restrict__ rel) {
    int i = blockIdx.x * blockDim.x + threadIdx.x;
    int totE = Nn * Fd / 4, totR = Rr * Fd / 4;
    if (i < totE) {
        float4 v = *(const float4*)(ent + (size_t)i * 4);
        *(uint2*)&g_entH[(size_t)i * 4] = pack4h(v);
    } else if (i < totE + totR) {
        int j = i - totE;
        float4 v = *(const float4*)(rel + (size_t)j * 4);
        *(uint2*)&g_relH[(size_t)j * 4] = pack4h(v);
    }
}

// ---------------- init mean + softmax partition sums (one CSR pass, no max needed) ----------------
__global__ void k_initstats() {
    int w = (blockIdx.x * blockDim.x + threadIdx.x) >> 5;
    int lane = threadIdx.x & 31;
    if (w >= Nn) return;
    int b = g_off[w], e = g_off[w + 1];
    float z0 = 0.f, z1 = 0.f, z2 = 0.f, z3 = 0.f;
    for (int i = b + lane; i < e; i += 32) {
        float4 E = g_arelE[g_srel[i]];
        z0 += E.x; z1 += E.y; z2 += E.z; z3 += E.w;
    }
    z0 = wredsum(z0); z1 = wredsum(z1); z2 = wredsum(z2); z3 = wredsum(z3);
    if (lane == 0) {
        g_Z[w] = z0; g_Z[Nn + w] = z1; g_Z[2 * Nn + w] = z2; g_Z[3 * Nn + w] = z3;
    }
    float4 aE = make_float4(0.f, 0.f, 0.f, 0.f);
    float4 aR = make_float4(0.f, 0.f, 0.f, 0.f);
    for (int i = b; i < e; i++) {
        int s = g_ssrc[i], r = g_srel[i];
        uint2 ue = *(const uint2*)&g_entH[(size_t)s * Fd + lane * 4];
        uint2 ur = *(const uint2*)&g_relH[(size_t)r * Fd + lane * 4];
        float2 e0 = __half22float2(*(__half2*)&ue.x), e1 = __half22float2(*(__half2*)&ue.y);
        float2 r0 = __half22float2(*(__half2*)&ur.x), r1 = __half22float2(*(__half2*)&ur.y);
        aE.x += e0.x; aE.y += e0.y; aE.z += e1.x; aE.w += e1.y;
        aR.x += r0.x; aR.y += r0.y; aR.z += r1.x; aR.w += r1.y;
    }
    float inv = 1.f / fmaxf((float)(e - b), 1.f);
    float4 o0 = make_float4(tanhf(aE.x * inv), tanhf(aE.y * inv), tanhf(aE.z * inv), tanhf(aE.w * inv));
    float4 o1 = make_float4(tanhf(aR.x * inv), tanhf(aR.y * inv), tanhf(aR.z * inv), tanhf(aR.w * inv));
    int oidx = w * FDh + lane * 4;
    *(float4*)&g_out[0][oidx] = o0;
    *(float4*)&g_out[1][oidx] = o1;
    int hidx = w * Fd + lane * 4;
    *(uint2*)&g_fh0[0][hidx] = pack4h(o0);
    *(uint2*)&g_fh0[1][hidx] = pack4h(o1);
    *(uint2*)&g_ob[0][oidx] = pack4bf(o0);
    *(uint2*)&g_ob[1][oidx] = pack4bf(o1);
}

// ---------------- Householder + attention aggregation ----------------
__global__ void k_agg(int layer) {
    int w = (blockIdx.x * blockDim.x + threadIdx.x) >> 5;
    int lane = threadIdx.x & 31;
    if (w >= Nn) return;
    int b = g_off[w], e = g_off[w + 1];
    int oidx = w * FDh + (layer + 1) * Fd + lane * 4;
    int hidx = w * Fd + lane * 4;
    const __half* fsrc0 = layer == 0 ? g_fh0[0] : g_fh1[0];
    const __half* fsrc1 = layer == 0 ? g_fh0[1] : g_fh1[1];
    if (b == e) {
        float4 z = make_float4(0.f, 0.f, 0.f, 0.f);
        *(float4*)&g_out[0][oidx] = z;
        *(float4*)&g_out[1][oidx] = z;
        uint2 zu = make_uint2(0u, 0u);
        if (layer == 0) { *(uint2*)&g_fh1[0][hidx] = zu; *(uint2*)&g_fh1[1][hidx] = zu; }
        *(uint2*)&g_ob[0][oidx] = zu;
        *(uint2*)&g_ob[1][oidx] = zu;
        return;
    }
    int dl0 = layer, dl1 = 2 + layer;
    float Zi0 = 1.f / g_Z[dl0 * Nn + w];
    float Zi1 = 1.f / g_Z[dl1 * Nn + w];
    float4 a0 = make_float4(0.f, 0.f, 0.f, 0.f);
    float4 a1 = make_float4(0.f, 0.f, 0.f, 0.f);
    for (int i = b; i < e; i++) {
        int s = g_ssrc[i], r = g_srel[i];
        float4 E = g_arelE[r];
        float w0 = (layer == 0 ? E.x : E.y) * Zi0;
        float w1 = (layer == 0 ? E.z : E.w) * Zi1;
        uint2 urv = *(const uint2*)&g_rnH[(size_t)r * Fd + lane * 4];
        uint2 uf0 = *(const uint2*)&fsrc0[(size_t)s * Fd + lane * 4];
        uint2 uf1 = *(const uint2*)&fsrc1[(size_t)s * Fd + lane * 4];
        float2 rva = __half22float2(*(__half2*)&urv.x), rvb = __half22float2(*(__half2*)&urv.y);
        float2 f0a = __half22float2(*(__half2*)&uf0.x), f0b = __half22float2(*(__half2*)&uf0.y);
        float2 f1a = __half22float2(*(__half2*)&uf1.x), f1b = __half22float2(*(__half2*)&uf1.y);
        float p0 = f0a.x * rva.x + f0a.y * rva.y + f0b.x * rvb.x + f0b.y * rvb.y;
        float p1 = f1a.x * rva.x + f1a.y * rva.y + f1b.x * rvb.x + f1b.y * rvb.y;
        p0 = wredsum(p0) * 2.f;
        p1 = wredsum(p1) * 2.f;
        a0.x += w0 * (f0a.x - p0 * rva.x); a0.y += w0 * (f0a.y - p0 * rva.y);
        a0.z += w0 * (f0b.x - p0 * rvb.x); a0.w += w0 * (f0b.y - p0 * rvb.y);
        a1.x += w1 * (f1a.x - p1 * rva.x); a1.y += w1 * (f1a.y - p1 * rva.y);
        a1.z += w1 * (f1b.x - p1 * rvb.x); a1.w += w1 * (f1b.y - p1 * rvb.y);
    }
    float4 o0 = make_float4(tanhf(a0.x), tanhf(a0.y), tanhf(a0.z), tanhf(a0.w));
    float4 o1 = make_float4(tanhf(a1.x), tanhf(a1.y), tanhf(a1.z), tanhf(a1.w));
    *(float4*)&g_out[0][oidx] = o0;
    *(float4*)&g_out[1][oidx] = o1;
    if (layer == 0) {
        *(uint2*)&g_fh1[0][hidx] = pack4h(o0);
        *(uint2*)&g_fh1[1][hidx] = pack4h(o1);
    }
    *(uint2*)&g_ob[0][oidx] = pack4bf(o0);
    *(uint2*)&g_ob[1][oidx] = pack4bf(o1);
}

// ---------------- epilogue prep ----------------
__global__ void k_prep_gate(const float* __restrict__ ge, const float* __restrict__ gr) {
    int n = blockIdx.x, dual = blockIdx.y, k = threadIdx.x;
    const float* g = dual ? gr : ge;
    g_gateT[dual][n * FDh + k] = __float2bfloat16(g[k * FDh + n]);
}
__global__ void k_prep_proxy(const float* __restrict__ pe, const float* __restrict__ pr) {
    int p = blockIdx.x, dual = blockIdx.y, f = threadIdx.x;  // 384 threads
    const float* P = dual ? pr : pe;
    float v = P[p * FDh + f];
    __shared__ float sm[12];
    float s = wredsum(v * v);
    if ((f & 31) == 0) sm[f >> 5] = s;
    __syncthreads();
    float tot = 0.f;
#pragma unroll
    for (int i = 0; i < 12; i++) tot += sm[i];
    float nv = v / fmaxf(sqrtf(tot), EPSV);
    g_proxyN[dual][p * FDh + f] = __float2bfloat16(nv);
    __nv_bfloat16 h = __float2bfloat16(v);
    __nv_bfloat16 l = __float2bfloat16(v - __bfloat162float(h));
    g_PB3[dual][f * 192 + p] = h;
    g_PB3[dual][f * 192 + 64 + p] = l;
    g_PB3[dual][f * 192 + 128 + p] = h;
}
__global__ void k_prep_pg(const float* __restrict__ pe, const float* __restrict__ pr,
                          const float* __restrict__ ge, const float* __restrict__ gr) {
    int f = blockIdx.x, dual = blockIdx.y, p = threadIdx.x;  // 64 threads
    const float* P = dual ? pr : pe;
    const float* g = dual ? gr : ge;
    float acc = 0.f;
    for (int k = 0; k < FDh; k++) acc += P[p * FDh + k] * g[k * FDh + f];
    g_PGtn[dual][f * Pp + p] = __float2bfloat16(-acc);
}

// ---------------- inverse row norms of ob ----------------
__global__ void k_rnorm() {
    int w = (blockIdx.x * blockDim.x + threadIdx.x) >> 5;
    int lane = threadIdx.x & 31;
    int dual = blockIdx.y;
    if (w >= Nn) return;
    const __nv_bfloat16* row = &g_ob[dual][(size_t)w * FDh];
    float s = 0.f;
#pragma unroll
    for (int k = 0; k < 3; k++) {
        uint2 u = *(const uint2*)&row[lane * 4 + k * 128];
        float2 a = __bfloat1622float2(*(__nv_bfloat162*)&u.x);
        float2 b = __bfloat1622float2(*(__nv_bfloat162*)&u.y);
        s += a.x * a.x + a.y * a.y + b.x * b.x + b.y * b.y;
    }
    s = wredsum(s);
    if (lane == 0) g_rnorm[dual * Nn + w] = 1.f / fmaxf(sqrtf(s), EPSV);
}

// ---------------- S GEMM (on raw ob, scaled by rnorm) + softmax -> SA3 (hi|hi|lo) ----------------
__global__ void __launch_bounds__(256) k_S() {
    __shared__ __align__(16) char sbuf[49152];
    __nv_bfloat16* As0 = (__nv_bfloat16*)sbuf;
    __nv_bfloat16* As1 = As0 + 8192;
    __nv_bfloat16* Bs0 = As1 + 8192;
    __nv_bfloat16* Bs1 = Bs0 + 4096;
    int t = threadIdx.x, lane = t & 31, wid = t >> 5;
    int wm = wid >> 1, wn = wid & 1;
    int dual = blockIdx.z;
    int row0 = blockIdx.x * 128;
    float acc[2][4][4];
#pragma unroll
    for (int a = 0; a < 2; a++)
#pragma unroll
        for (int bq = 0; bq < 4; bq++)
#pragma unroll
            for (int c = 0; c < 4; c++) acc[a][bq][c] = 0.f;
    gemm_phase(acc, g_ob[dual], 384, row0, Nn, g_proxyN[dual], 384, 0, 384,
               As0, As1, Bs0, Bs1, t, wm, wn, lane);
    float* Sf = (float*)sbuf;
#pragma unroll
    for (int mt = 0; mt < 2; mt++)
#pragma unroll
        for (int n8 = 0; n8 < 4; n8++) {
            int row = wm * 32 + mt * 16 + (lane >> 2);
            int col = wn * 32 + n8 * 8 + (lane & 3) * 2;
            Sf[row * 64 + col] = acc[mt][n8][0];
            Sf[row * 64 + col + 1] = acc[mt][n8][1];
            Sf[(row + 8) * 64 + col] = acc[mt][n8][2];
            Sf[(row + 8) * 64 + col + 1] = acc[mt][n8][3];
        }
    __syncthreads();
    for (int rr = 0; rr < 16; rr++) {
        int row = wid * 16 + rr;
        int gn = row0 + row;
        if (gn < Nn) {
            float inv = g_rnorm[dual * Nn + gn];
            float v0 = Sf[row * 64 + lane] * inv, v1 = Sf[row * 64 + 32 + lane] * inv;
            float m = wredmax(fmaxf(v0, v1));
            float e0 = expf(v0 - m), e1 = expf(v1 - m);
            float s = wredsum(e0 + e1);
            float r0 = e0 / s, r1 = e1 / s;
            __nv_bfloat16 h0 = __float2bfloat16(r0), h1 = __float2bfloat16(r1);
            __nv_bfloat16 l0 = __float2bfloat16(r0 - __bfloat162float(h0));
            __nv_bfloat16 l1 = __float2bfloat16(r1 - __bfloat162float(h1));
            __nv_bfloat16* dstp = &g_SA3[dual][(size_t)gn * 192];
            dstp[lane] = h0; dstp[32 + lane] = h1;
            dstp[64 + lane] = h0; dstp[96 + lane] = h1;
            dstp[128 + lane] = l0; dstp[160 + lane] = l1;
        }
    }
}

// ---------------- final fused GEMMs + combine (streaming, 48KB smem) ----------------
__global__ void __launch_bounds__(256) k_final(const float* __restrict__ be,
                                               const float* __restrict__ br,
                                               float* __restrict__ out) {
    __shared__ __align__(16) char sbuf[49152];
    __nv_bfloat16* As0 = (__nv_bfloat16*)sbuf;
    __nv_bfloat16* As1 = As0 + 8192;
    __nv_bfloat16* Bs0 = As1 + 8192;
    __nv_bfloat16* Bs1 = Bs0 + 4096;
    int t = threadIdx.x, lane = t & 31, wid = t >> 5;
    int wm = wid >> 1, wn = wid & 1;
    int row0 = blockIdx.x * 128, col0 = blockIdx.y * 64, dual = blockIdx.z;
    float accZ[2][4][4], accS[2][4][4];
#pragma unroll
    for (int a = 0; a < 2; a++)
#pragma unroll
        for (int bq = 0; bq < 4; bq++)
#pragma unroll
            for (int c = 0; c < 4; c++) { accZ[a][bq][c] = 0.f; accS[a][bq][c] = 0.f; }
    gemm_phase(accZ, g_ob[dual], 384, row0, Nn, g_gateT[dual], 384, col0, 384,
               As0, As1, Bs0, Bs1, t, wm, wn, lane);
    gemm_phase(accZ, g_SA3[dual], 192, row0, Nn, g_PGtn[dual], Pp, col0, 64,
               As0, As1, Bs0, Bs1, t, wm, wn, lane);
    gemm_phase(accS, g_SA3[dual], 192, row0, Nn, g_PB3[dual], 192, col0, 192,
               As0, As1, Bs0, Bs1, t, wm, wn, lane);
    const float* bias = dual ? br : be;
#pragma unroll
    for (int mt = 0; mt < 2; mt++)
#pragma unroll
        for (int n8 = 0; n8 < 4; n8++) {
            int rbase = wm * 32 + mt * 16 + (lane >> 2);
            int gc = col0 + wn * 32 + n8 * 8 + (lane & 3) * 2;
            float b0 = bias[gc], b1 = bias[gc + 1];
#pragma unroll
            for (int h = 0; h < 2; h++) {
                int gr = row0 + rbase + h * 8;
                if (gr < Nn) {
                    float z0 = accZ[mt][n8][h * 2], z1 = accZ[mt][n8][h * 2 + 1];
                    float s0 = accS[mt][n8][h * 2], s1 = accS[mt][n8][h * 2 + 1];
                    float2 ov = *(const float2*)&g_out[dual][(size_t)gr * FDh + gc];
                    float gt0 = 1.f / (1.f + expf(-(z0 + b0)));
                    float gt1 = 1.f / (1.f + expf(-(z1 + b1)));
                    float o0 = ov.x - (1.f - gt0) * s0;
                    float o1 = ov.y - (1.f - gt1) * s1;
                    *(float2*)&out[(size_t)gr * 768 + dual * 384 + gc] = make_float2(o0, o1);
                }
            }
        }
}

// ---------------- launch ----------------
extern "C" void kernel_launch(void* const* d_in, const int* in_sizes, int n_in,
                              void* d_out, int out_size) {
    const float* ent = (const float*)d_in[0];
    const float* rel = (const float*)d_in[1];
    const int* esrc = (const int*)d_in[2];
    const int* edst = (const int*)d_in[3];
    const int* erel = (const int*)d_in[4];
    const float* attn_e = (const float*)d_in[5];
    const float* gate_e = (const float*)d_in[6];
    const float* proxy_e = (const float*)d_in[7];
    const float* bias_e = (const float*)d_in[8];
    const float* attn_r = (const float*)d_in[9];
    const float* gate_r = (const float*)d_in[10];
    const float* proxy_r = (const float*)d_in[11];
    const float* bias_r = (const float*)d_in[12];
    float* out = (float*)d_out;

    k_zero<<<(Nn + 255) / 256, 256>>>();
    k_count<<<(Ne + 255) / 256, 256>>>(edst);
    k_scan<<<1, 1024>>>();
    k_scatter<<<(Ne + 255) / 256, 256>>>(esrc, edst, erel);
    k_relnorm<<<Rr, 128>>>(rel, attn_e, attn_r);

    int convTot = (Nn + Rr) * Fd / 4;
    k_conv16<<<(convTot + 255) / 256, 256>>>(ent, rel);

    int wblocks = (Nn + 7) / 8;
    k_initstats<<<wblocks, 256>>>();
    k_agg<<<wblocks, 256>>>(0);
    k_agg<<<wblocks, 256>>>(1);

    k_prep_gate<<<dim3(FDh, 2), FDh>>>(gate_e, gate_r);
    k_prep_proxy<<<dim3(Pp, 2), FDh>>>(proxy_e, proxy_r);
    k_prep_pg<<<dim3(FDh, 2), Pp>>>(proxy_e, proxy_r, gate_e, gate_r);
    k_rnorm<<<dim3(wblocks, 2), 256>>>();

    int mblocks = (Nn + 127) / 128;
    k_S<<<dim3(mblocks, 1, 2), 256>>>();
    k_final<<<dim3(mblocks, 6, 2), 256>>>(bias_e, bias_r, out);
}

// round 11
// speedup vs baseline: 1.4223x; 1.0589x over previous
#include <cuda_runtime.h>
#include <cuda_bf16.h>
#include <cuda_fp16.h>
#include <cstdint>

#define Nn 50000
#define Ne 800000
#define Rr 2000
#define Fd 128
#define FDh 384
#define Pp 64
#define EPSV 1e-12f

// ---------------- static scratch ----------------
__device__ int g_cnt[Nn];
__device__ int g_off[Nn + 1];
__device__ int g_ssrc[Ne];
__device__ int g_srel[Ne];
__device__ float4 g_arelE[Rr];          // exp(attention logit) for the 4 (dual,layer) combos
__device__ float g_Z[4 * Nn];
__device__ float g_rnorm[2 * Nn];
__device__ __align__(16) __half g_entH[Nn * Fd];
__device__ __align__(16) __half g_relH[Rr * Fd];
__device__ __align__(16) __half g_rnH[Rr * Fd];
__device__ __align__(16) __half g_fh0[2][Nn * Fd];   // slice 0 (init feats), fp16
__device__ __align__(16) __half g_fh1[2][Nn * Fd];   // slice 1 (layer-0 out), fp16
__device__ __align__(16) __half g_fh2[2][Nn * Fd];   // slice 2 (layer-1 out), fp16
__device__ __align__(16) __nv_bfloat16 g_gateT[2][FDh * FDh];
__device__ __align__(16) __nv_bfloat16 g_proxyN[2][Pp * FDh];
__device__ __align__(16) __nv_bfloat16 g_PGtn[2][FDh * Pp];
__device__ __align__(16) __nv_bfloat16 g_PB3[2][FDh * 192];
__device__ __align__(16) __nv_bfloat16 g_ob[2][Nn * FDh];
__device__ __align__(16) __nv_bfloat16 g_SA3[2][Nn * 192];

// ---------------- helpers ----------------
__device__ __forceinline__ float wredsum(float v) {
#pragma unroll
    for (int o = 16; o; o >>= 1) v += __shfl_xor_sync(0xffffffffu, v, o);
    return v;
}
__device__ __forceinline__ float wredmax(float v) {
#pragma unroll
    for (int o = 16; o; o >>= 1) v = fmaxf(v, __shfl_xor_sync(0xffffffffu, v, o));
    return v;
}
// 4 independent butterfly reductions, interleaved for shfl-latency hiding
__device__ __forceinline__ void wredsum4(float& a, float& b, float& c, float& d) {
#pragma unroll
    for (int o = 16; o; o >>= 1) {
        float ta = __shfl_xor_sync(0xffffffffu, a, o);
        float tb = __shfl_xor_sync(0xffffffffu, b, o);
        float tc = __shfl_xor_sync(0xffffffffu, c, o);
        float td = __shfl_xor_sync(0xffffffffu, d, o);
        a += ta; b += tb; c += tc; d += td;
    }
}

__device__ __forceinline__ int swz(int r, int c) {  // halves; c multiple of 8
    return r * 64 + (c ^ ((r & 7) << 3));
}

__device__ __forceinline__ void ldm4(unsigned* r, const void* p) {
    unsigned a = (unsigned)__cvta_generic_to_shared(p);
    asm volatile("ldmatrix.sync.aligned.m8n8.x4.shared.b16 {%0,%1,%2,%3},[%4];"
                 : "=r"(r[0]), "=r"(r[1]), "=r"(r[2]), "=r"(r[3]) : "r"(a));
}

__device__ __forceinline__ void mma16816(float* c, unsigned a0, unsigned a1,
                                         unsigned a2, unsigned a3,
                                         unsigned b0, unsigned b1) {
    asm volatile(
        "mma.sync.aligned.m16n8k16.row.col.f32.bf16.bf16.f32 "
        "{%0,%1,%2,%3},{%4,%5,%6,%7},{%8,%9},{%0,%1,%2,%3};\n"
        : "+f"(c[0]), "+f"(c[1]), "+f"(c[2]), "+f"(c[3])
        : "r"(a0), "r"(a1), "r"(a2), "r"(a3), "r"(b0), "r"(b1));
}

__device__ __forceinline__ void cpa16(__nv_bfloat16* dst, const void* src, bool pred) {
    unsigned d = (unsigned)__cvta_generic_to_shared(dst);
    int sz = pred ? 16 : 0;
    asm volatile("cp.async.cg.shared.global [%0], [%1], 16, %2;" :: "r"(d), "l"(src), "r"(sz));
}

__device__ __forceinline__ uint2 pack4bf(float4 v) {
    __nv_bfloat162 p0 = __floats2bfloat162_rn(v.x, v.y);
    __nv_bfloat162 p1 = __floats2bfloat162_rn(v.z, v.w);
    return make_uint2(*(unsigned*)&p0, *(unsigned*)&p1);
}
__device__ __forceinline__ uint2 pack4h(float4 v) {
    __half2 h0 = __floats2half2_rn(v.x, v.y);
    __half2 h1 = __floats2half2_rn(v.z, v.w);
    return make_uint2(*(unsigned*)&h0, *(unsigned*)&h1);
}

// ===== GEMM machinery (swizzled, streamed, double-buffered) =====
__device__ __forceinline__ void loadA_a(__nv_bfloat16* As, const __nv_bfloat16* A,
                                        int row0, int lda, int kt, int t, int rowmax) {
#pragma unroll
    for (int i = 0; i < 4; i++) {
        int idx = t + i * 256;
        int r = idx >> 3, c = (idx & 7) * 8;
        int gr = row0 + r;
        int cr = gr < rowmax ? gr : rowmax - 1;
        cpa16(As + swz(r, c), A + (size_t)cr * lda + kt + c, gr < rowmax);
    }
}
__device__ __forceinline__ void loadB_a(__nv_bfloat16* Bs, const __nv_bfloat16* B,
                                        int col0, int ldb, int kt, int t) {
#pragma unroll
    for (int i = 0; i < 2; i++) {
        int idx = t + i * 256;
        int r = idx >> 3, c = (idx & 7) * 8;
        cpa16(Bs + swz(r, c), B + (size_t)(col0 + r) * ldb + kt + c, true);
    }
}
__device__ __forceinline__ void mmastep64(float (&acc)[2][4][4], const __nv_bfloat16* As,
                                          const __nv_bfloat16* Bs, int wm, int wn, int lane) {
    int lr = lane & 15, lc = (lane >> 4) * 8;
#pragma unroll
    for (int kk = 0; kk < 64; kk += 16) {
        unsigned ra[2][4], rb[2][4];
        ldm4(ra[0], As + swz(wm * 32 + lr, kk + lc));
        ldm4(ra[1], As + swz(wm * 32 + 16 + lr, kk + lc));
        ldm4(rb[0], Bs + swz(wn * 32 + lr, kk + lc));
        ldm4(rb[1], Bs + swz(wn * 32 + 16 + lr, kk + lc));
#pragma unroll
        for (int mt = 0; mt < 2; mt++) {
            mma16816(acc[mt][0], ra[mt][0], ra[mt][1], ra[mt][2], ra[mt][3], rb[0][0], rb[0][2]);
            mma16816(acc[mt][1], ra[mt][0], ra[mt][1], ra[mt][2], ra[mt][3], rb[0][1], rb[0][3]);
            mma16816(acc[mt][2], ra[mt][0], ra[mt][1], ra[mt][2], ra[mt][3], rb[1][0], rb[1][2]);
            mma16816(acc[mt][3], ra[mt][0], ra[mt][1], ra[mt][2], ra[mt][3], rb[1][1], rb[1][3]);
        }
    }
}
__device__ __forceinline__ void gemm_phase(float (&acc)[2][4][4],
                                           const __nv_bfloat16* A, int lda, int row0, int rowmax,
                                           const __nv_bfloat16* B, int ldb, int col0, int Ktot,
                                           __nv_bfloat16* As0, __nv_bfloat16* As1,
                                           __nv_bfloat16* Bs0, __nv_bfloat16* Bs1,
                                           int t, int wm, int wn, int lane) {
    int nt = Ktot >> 6;
    __nv_bfloat16* Ab[2] = {As0, As1};
    __nv_bfloat16* Bb[2] = {Bs0, Bs1};
    loadA_a(Ab[0], A, row0, lda, 0, t, rowmax);
    loadB_a(Bb[0], B, col0, ldb, 0, t);
    asm volatile("cp.async.commit_group;");
    for (int k = 0; k < nt; k++) {
        if (k + 1 < nt) {
            loadA_a(Ab[(k + 1) & 1], A, row0, lda, (k + 1) << 6, t, rowmax);
            loadB_a(Bb[(k + 1) & 1], B, col0, ldb, (k + 1) << 6, t);
            asm volatile("cp.async.commit_group;");
            asm volatile("cp.async.wait_group 1;");
        } else {
            asm volatile("cp.async.wait_group 0;");
        }
        __syncthreads();
        mmastep64(acc, Ab[k & 1], Bb[k & 1], wm, wn, lane);
        __syncthreads();
    }
}

// ---------------- CSR build ----------------
__global__ void k_zero() {
    int i = blockIdx.x * blockDim.x + threadIdx.x;
    if (i < Nn) g_cnt[i] = 0;
}
__global__ void k_count(const int* __restrict__ dst) {
    int e = blockIdx.x * blockDim.x + threadIdx.x;
    if (e < Ne) atomicAdd(&g_cnt[dst[e]], 1);
}
__global__ void k_scan() {
    __shared__ int wsum[32];
    __shared__ int carry;
    int t = threadIdx.x, lane = t & 31, wid = t >> 5;
    if (t == 0) { carry = 0; g_off[0] = 0; }
    __syncthreads();
    for (int base = 0; base < Nn; base += 1024) {
        int i = base + t;
        int v = (i < Nn) ? g_cnt[i] : 0;
        if (i < Nn) g_cnt[i] = 0;
        int x = v;
#pragma unroll
        for (int o = 1; o < 32; o <<= 1) {
            int y = __shfl_up_sync(0xffffffffu, x, o);
            if (lane >= o) x += y;
        }
        if (lane == 31) wsum[wid] = x;
        __syncthreads();
        if (wid == 0) {
            int s = wsum[lane];
#pragma unroll
            for (int o = 1; o < 32; o <<= 1) {
                int y = __shfl_up_sync(0xffffffffu, s, o);
                if (lane >= o) s += y;
            }
            wsum[lane] = s;
        }
        __syncthreads();
        int pre = (wid > 0) ? wsum[wid - 1] : 0;
        int inc = x + pre + carry;
        if (i < Nn) g_off[i + 1] = inc;
        __syncthreads();
        if (t == 1023) carry = inc;
        __syncthreads();
    }
}
__global__ void k_scatter(const int* __restrict__ src, const int* __restrict__ dst,
                          const int* __restrict__ rel) {
    int e = blockIdx.x * blockDim.x + threadIdx.x;
    if (e < Ne) {
        int d = dst[e];
        int p = g_off[d] + atomicAdd(&g_cnt[d], 1);
        g_ssrc[p] = src[e];
        g_srel[p] = rel[e];
    }
}

// ---------------- relation precompute ----------------
__global__ void k_relnorm(const float* __restrict__ rel, const float* __restrict__ ae,
                          const float* __restrict__ ar) {
    int r = blockIdx.x;
    int t = threadIdx.x;  // 128
    float v = rel[r * Fd + t];
    float s = wredsum(v * v);
    __shared__ float sm[4];
    __shared__ float sm4[4][4];
    if ((t & 31) == 0) sm[t >> 5] = s;
    __syncthreads();
    float tot = sm[0] + sm[1] + sm[2] + sm[3];
    float nv = v / fmaxf(sqrtf(tot), EPSV);
    g_rnH[r * Fd + t] = __float2half(nv);
    float d0 = wredsum(nv * ae[t]);
    float d1 = wredsum(nv * ae[Fd + t]);
    float d2 = wredsum(nv * ar[t]);
    float d3 = wredsum(nv * ar[Fd + t]);
    if ((t & 31) == 0) {
        sm4[0][t >> 5] = d0; sm4[1][t >> 5] = d1;
        sm4[2][t >> 5] = d2; sm4[3][t >> 5] = d3;
    }
    __syncthreads();
    if (t == 0) {
        float4 E;
        E.x = expf(sm4[0][0] + sm4[0][1] + sm4[0][2] + sm4[0][3]);
        E.y = expf(sm4[1][0] + sm4[1][1] + sm4[1][2] + sm4[1][3]);
        E.z = expf(sm4[2][0] + sm4[2][1] + sm4[2][2] + sm4[2][3]);
        E.w = expf(sm4[3][0] + sm4[3][1] + sm4[3][2] + sm4[3][3]);
        g_arelE[r] = E;
    }
}

// ---------------- fp32 -> fp16 of inputs ----------------
__global__ void k_conv16(const float* __restrict__ ent, const float* __restrict__ rel) {
    int i = blockIdx.x * blockDim.x + threadIdx.x;
    int totE = Nn * Fd / 4, totR = Rr * Fd / 4;
    if (i < totE) {
        float4 v = *(const float4*)(ent + (size_t)i * 4);
        *(uint2*)&g_entH[(size_t)i * 4] = pack4h(v);
    } else if (i < totE + totR) {
        int j = i - totE;
        float4 v = *(const float4*)(rel + (size_t)j * 4);
        *(uint2*)&g_relH[(size_t)j * 4] = pack4h(v);
    }
}

// ---------------- init mean + softmax partition sums ----------------
__global__ void k_initstats() {
    int w = (blockIdx.x * blockDim.x + threadIdx.x) >> 5;
    int lane = threadIdx.x & 31;
    if (w >= Nn) return;
    int b = g_off[w], e = g_off[w + 1];
    float z0 = 0.f, z1 = 0.f, z2 = 0.f, z3 = 0.f;
    for (int i = b + lane; i < e; i += 32) {
        float4 E = g_arelE[g_srel[i]];
        z0 += E.x; z1 += E.y; z2 += E.z; z3 += E.w;
    }
    wredsum4(z0, z1, z2, z3);
    if (lane == 0) {
        g_Z[w] = z0; g_Z[Nn + w] = z1; g_Z[2 * Nn + w] = z2; g_Z[3 * Nn + w] = z3;
    }
    float4 aE = make_float4(0.f, 0.f, 0.f, 0.f);
    float4 aR = make_float4(0.f, 0.f, 0.f, 0.f);
    for (int i = b; i < e; i++) {
        int s = g_ssrc[i], r = g_srel[i];
        uint2 ue = *(const uint2*)&g_entH[(size_t)s * Fd + lane * 4];
        uint2 ur = *(const uint2*)&g_relH[(size_t)r * Fd + lane * 4];
        float2 e0 = __half22float2(*(__half2*)&ue.x), e1 = __half22float2(*(__half2*)&ue.y);
        float2 r0 = __half22float2(*(__half2*)&ur.x), r1 = __half22float2(*(__half2*)&ur.y);
        aE.x += e0.x; aE.y += e0.y; aE.z += e1.x; aE.w += e1.y;
        aR.x += r0.x; aR.y += r0.y; aR.z += r1.x; aR.w += r1.y;
    }
    float inv = 1.f / fmaxf((float)(e - b), 1.f);
    float4 o0 = make_float4(tanhf(aE.x * inv), tanhf(aE.y * inv), tanhf(aE.z * inv), tanhf(aE.w * inv));
    float4 o1 = make_float4(tanhf(aR.x * inv), tanhf(aR.y * inv), tanhf(aR.z * inv), tanhf(aR.w * inv));
    int oidx = w * FDh + lane * 4;
    int hidx = w * Fd + lane * 4;
    *(uint2*)&g_fh0[0][hidx] = pack4h(o0);
    *(uint2*)&g_fh0[1][hidx] = pack4h(o1);
    *(uint2*)&g_ob[0][oidx] = pack4bf(o0);
    *(uint2*)&g_ob[1][oidx] = pack4bf(o1);
}

// ---------------- Householder + attention aggregation ----------------
__global__ void k_agg(int layer) {
    int w = (blockIdx.x * blockDim.x + threadIdx.x) >> 5;
    int lane = threadIdx.x & 31;
    if (w >= Nn) return;
    int b = g_off[w], e = g_off[w + 1];
    int oidx = w * FDh + (layer + 1) * Fd + lane * 4;
    int hidx = w * Fd + lane * 4;
    const __half* fsrc0 = layer == 0 ? g_fh0[0] : g_fh1[0];
    const __half* fsrc1 = layer == 0 ? g_fh0[1] : g_fh1[1];
    __half* fdst0 = layer == 0 ? g_fh1[0] : g_fh2[0];
    __half* fdst1 = layer == 0 ? g_fh1[1] : g_fh2[1];
    if (b == e) {
        uint2 zu = make_uint2(0u, 0u);
        *(uint2*)&fdst0[hidx] = zu;
        *(uint2*)&fdst1[hidx] = zu;
        *(uint2*)&g_ob[0][oidx] = zu;
        *(uint2*)&g_ob[1][oidx] = zu;
        return;
    }
    int dl0 = layer, dl1 = 2 + layer;
    float Zi0 = 1.f / g_Z[dl0 * Nn + w];
    float Zi1 = 1.f / g_Z[dl1 * Nn + w];
    float4 a0 = make_float4(0.f, 0.f, 0.f, 0.f);
    float4 a1 = make_float4(0.f, 0.f, 0.f, 0.f);
    int i = b;
    for (; i + 1 < e; i += 2) {
        int sA = g_ssrc[i], rA = g_srel[i];
        int sB = g_ssrc[i + 1], rB = g_srel[i + 1];
        float4 EA = g_arelE[rA], EB = g_arelE[rB];
        float wA0 = (layer == 0 ? EA.x : EA.y) * Zi0;
        float wA1 = (layer == 0 ? EA.z : EA.w) * Zi1;
        float wB0 = (layer == 0 ? EB.x : EB.y) * Zi0;
        float wB1 = (layer == 0 ? EB.z : EB.w) * Zi1;
        uint2 urvA = *(const uint2*)&g_rnH[(size_t)rA * Fd + lane * 4];
        uint2 uf0A = *(const uint2*)&fsrc0[(size_t)sA * Fd + lane * 4];
        uint2 uf1A = *(const uint2*)&fsrc1[(size_t)sA * Fd + lane * 4];
        uint2 urvB = *(const uint2*)&g_rnH[(size_t)rB * Fd + lane * 4];
        uint2 uf0B = *(const uint2*)&fsrc0[(size_t)sB * Fd + lane * 4];
        uint2 uf1B = *(const uint2*)&fsrc1[(size_t)sB * Fd + lane * 4];
        float2 rvAa = __half22float2(*(__half2*)&urvA.x), rvAb = __half22float2(*(__half2*)&urvA.y);
        float2 f0Aa = __half22float2(*(__half2*)&uf0A.x), f0Ab = __half22float2(*(__half2*)&uf0A.y);
        float2 f1Aa = __half22float2(*(__half2*)&uf1A.x), f1Ab = __half22float2(*(__half2*)&uf1A.y);
        float2 rvBa = __half22float2(*(__half2*)&urvB.x), rvBb = __half22float2(*(__half2*)&urvB.y);
        float2 f0Ba = __half22float2(*(__half2*)&uf0B.x), f0Bb = __half22float2(*(__half2*)&uf0B.y);
        float2 f1Ba = __half22float2(*(__half2*)&uf1B.x), f1Bb = __half22float2(*(__half2*)&uf1B.y);
        float pA0 = f0Aa.x * rvAa.x + f0Aa.y * rvAa.y + f0Ab.x * rvAb.x + f0Ab.y * rvAb.y;
        float pA1 = f1Aa.x * rvAa.x + f1Aa.y * rvAa.y + f1Ab.x * rvAb.x + f1Ab.y * rvAb.y;
        float pB0 = f0Ba.x * rvBa.x + f0Ba.y * rvBa.y + f0Bb.x * rvBb.x + f0Bb.y * rvBb.y;
        float pB1 = f1Ba.x * rvBa.x + f1Ba.y * rvBa.y + f1Bb.x * rvBb.x + f1Bb.y * rvBb.y;
        wredsum4(pA0, pA1, pB0, pB1);
        pA0 *= 2.f; pA1 *= 2.f; pB0 *= 2.f; pB1 *= 2.f;
        a0.x += wA0 * (f0Aa.x - pA0 * rvAa.x); a0.y += wA0 * (f0Aa.y - pA0 * rvAa.y);
        a0.z += wA0 * (f0Ab.x - pA0 * rvAb.x); a0.w += wA0 * (f0Ab.y - pA0 * rvAb.y);
        a1.x += wA1 * (f1Aa.x - pA1 * rvAa.x); a1.y += wA1 * (f1Aa.y - pA1 * rvAa.y);
        a1.z += wA1 * (f1Ab.x - pA1 * rvAb.x); a1.w += wA1 * (f1Ab.y - pA1 * rvAb.y);
        a0.x += wB0 * (f0Ba.x - pB0 * rvBa.x); a0.y += wB0 * (f0Ba.y - pB0 * rvBa.y);
        a0.z += wB0 * (f0Bb.x - pB0 * rvBb.x); a0.w += wB0 * (f0Bb.y - pB0 * rvBb.y);
        a1.x += wB1 * (f1Ba.x - pB1 * rvBa.x); a1.y += wB1 * (f1Ba.y - pB1 * rvBa.y);
        a1.z += wB1 * (f1Bb.x - pB1 * rvBb.x); a1.w += wB1 * (f1Bb.y - pB1 * rvBb.y);
    }
    if (i < e) {
        int s = g_ssrc[i], r = g_srel[i];
        float4 E = g_arelE[r];
        float w0 = (layer == 0 ? E.x : E.y) * Zi0;
        float w1 = (layer == 0 ? E.z : E.w) * Zi1;
        uint2 urv = *(const uint2*)&g_rnH[(size_t)r * Fd + lane * 4];
        uint2 uf0 = *(const uint2*)&fsrc0[(size_t)s * Fd + lane * 4];
        uint2 uf1 = *(const uint2*)&fsrc1[(size_t)s * Fd + lane * 4];
        float2 rva = __half22float2(*(__half2*)&urv.x), rvb = __half22float2(*(__half2*)&urv.y);
        float2 f0a = __half22float2(*(__half2*)&uf0.x), f0b = __half22float2(*(__half2*)&uf0.y);
        float2 f1a = __half22float2(*(__half2*)&uf1.x), f1b = __half22float2(*(__half2*)&uf1.y);
        float p0 = f0a.x * rva.x + f0a.y * rva.y + f0b.x * rvb.x + f0b.y * rvb.y;
        float p1 = f1a.x * rva.x + f1a.y * rva.y + f1b.x * rvb.x + f1b.y * rvb.y;
        p0 = wredsum(p0) * 2.f;
        p1 = wredsum(p1) * 2.f;
        a0.x += w0 * (f0a.x - p0 * rva.x); a0.y += w0 * (f0a.y - p0 * rva.y);
        a0.z += w0 * (f0b.x - p0 * rvb.x); a0.w += w0 * (f0b.y - p0 * rvb.y);
        a1.x += w1 * (f1a.x - p1 * rva.x); a1.y += w1 * (f1a.y - p1 * rva.y);
        a1.z += w1 * (f1b.x - p1 * rvb.x); a1.w += w1 * (f1b.y - p1 * rvb.y);
    }
    float4 o0 = make_float4(tanhf(a0.x), tanhf(a0.y), tanhf(a0.z), tanhf(a0.w));
    float4 o1 = make_float4(tanhf(a1.x), tanhf(a1.y), tanhf(a1.z), tanhf(a1.w));
    *(uint2*)&fdst0[hidx] = pack4h(o0);
    *(uint2*)&fdst1[hidx] = pack4h(o1);
    *(uint2*)&g_ob[0][oidx] = pack4bf(o0);
    *(uint2*)&g_ob[1][oidx] = pack4bf(o1);
}

// ---------------- epilogue prep ----------------
__global__ void k_prep_gate(const float* __restrict__ ge, const float* __restrict__ gr) {
    int n = blockIdx.x, dual = blockIdx.y, k = threadIdx.x;
    const float* g = dual ? gr : ge;
    g_gateT[dual][n * FDh + k] = __float2bfloat16(g[k * FDh + n]);
}
__global__ void k_prep_proxy(const float* __restrict__ pe, const float* __restrict__ pr) {
    int p = blockIdx.x, dual = blockIdx.y, f = threadIdx.x;  // 384 threads
    const float* P = dual ? pr : pe;
    float v = P[p * FDh + f];
    __shared__ float sm[12];
    float s = wredsum(v * v);
    if ((f & 31) == 0) sm[f >> 5] = s;
    __syncthreads();
    float tot = 0.f;
#pragma unroll
    for (int i = 0; i < 12; i++) tot += sm[i];
    float nv = v / fmaxf(sqrtf(tot), EPSV);
    g_proxyN[dual][p * FDh + f] = __float2bfloat16(nv);
    __nv_bfloat16 h = __float2bfloat16(v);
    __nv_bfloat16 l = __float2bfloat16(v - __bfloat162float(h));
    g_PB3[dual][f * 192 + p] = h;
    g_PB3[dual][f * 192 + 64 + p] = l;
    g_PB3[dual][f * 192 + 128 + p] = h;
}
__global__ void k_prep_pg(const float* __restrict__ pe, const float* __restrict__ pr,
                          const float* __restrict__ ge, const float* __restrict__ gr) {
    int f = blockIdx.x, dual = blockIdx.y, p = threadIdx.x;  // 64 threads
    const float* P = dual ? pr : pe;
    const float* g = dual ? gr : ge;
    float acc = 0.f;
    for (int k = 0; k < FDh; k++) acc += P[p * FDh + k] * g[k * FDh + f];
    g_PGtn[dual][f * Pp + p] = __float2bfloat16(-acc);
}

// ---------------- inverse row norms of ob ----------------
__global__ void k_rnorm() {
    int w = (blockIdx.x * blockDim.x + threadIdx.x) >> 5;
    int lane = threadIdx.x & 31;
    int dual = blockIdx.y;
    if (w >= Nn) return;
    const __nv_bfloat16* row = &g_ob[dual][(size_t)w * FDh];
    float s = 0.f;
#pragma unroll
    for (int k = 0; k < 3; k++) {
        uint2 u = *(const uint2*)&row[lane * 4 + k * 128];
        float2 a = __bfloat1622float2(*(__nv_bfloat162*)&u.x);
        float2 b = __bfloat1622float2(*(__nv_bfloat162*)&u.y);
        s += a.x * a.x + a.y * a.y + b.x * b.x + b.y * b.y;
    }
    s = wredsum(s);
    if (lane == 0) g_rnorm[dual * Nn + w] = 1.f / fmaxf(sqrtf(s), EPSV);
}

// ---------------- S GEMM (on raw ob, scaled by rnorm) + softmax -> SA3 (hi|hi|lo) ----------------
__global__ void __launch_bounds__(256) k_S() {
    __shared__ __align__(16) char sbuf[49152];
    __nv_bfloat16* As0 = (__nv_bfloat16*)sbuf;
    __nv_bfloat16* As1 = As0 + 8192;
    __nv_bfloat16* Bs0 = As1 + 8192;
    __nv_bfloat16* Bs1 = Bs0 + 4096;
    int t = threadIdx.x, lane = t & 31, wid = t >> 5;
    int wm = wid >> 1, wn = wid & 1;
    int dual = blockIdx.z;
    int row0 = blockIdx.x * 128;
    float acc[2][4][4];
#pragma unroll
    for (int a = 0; a < 2; a++)
#pragma unroll
        for (int bq = 0; bq < 4; bq++)
#pragma unroll
            for (int c = 0; c < 4; c++) acc[a][bq][c] = 0.f;
    gemm_phase(acc, g_ob[dual], 384, row0, Nn, g_proxyN[dual], 384, 0, 384,
               As0, As1, Bs0, Bs1, t, wm, wn, lane);
    float* Sf = (float*)sbuf;
#pragma unroll
    for (int mt = 0; mt < 2; mt++)
#pragma unroll
        for (int n8 = 0; n8 < 4; n8++) {
            int row = wm * 32 + mt * 16 + (lane >> 2);
            int col = wn * 32 + n8 * 8 + (lane & 3) * 2;
            Sf[row * 64 + col] = acc[mt][n8][0];
            Sf[row * 64 + col + 1] = acc[mt][n8][1];
            Sf[(row + 8) * 64 + col] = acc[mt][n8][2];
            Sf[(row + 8) * 64 + col + 1] = acc[mt][n8][3];
        }
    __syncthreads();
    for (int rr = 0; rr < 16; rr++) {
        int row = wid * 16 + rr;
        int gn = row0 + row;
        if (gn < Nn) {
            float inv = g_rnorm[dual * Nn + gn];
            float v0 = Sf[row * 64 + lane] * inv, v1 = Sf[row * 64 + 32 + lane] * inv;
            float m = wredmax(fmaxf(v0, v1));
            float e0 = expf(v0 - m), e1 = expf(v1 - m);
            float s = wredsum(e0 + e1);
            float r0 = e0 / s, r1 = e1 / s;
            __nv_bfloat16 h0 = __float2bfloat16(r0), h1 = __float2bfloat16(r1);
            __nv_bfloat16 l0 = __float2bfloat16(r0 - __bfloat162float(h0));
            __nv_bfloat16 l1 = __float2bfloat16(r1 - __bfloat162float(h1));
            __nv_bfloat16* dstp = &g_SA3[dual][(size_t)gn * 192];
            dstp[lane] = h0; dstp[32 + lane] = h1;
            dstp[64 + lane] = h0; dstp[96 + lane] = h1;
            dstp[128 + lane] = l0; dstp[160 + lane] = l1;
        }
    }
}

// ---------------- final fused GEMMs + combine (streaming, 48KB smem) ----------------
__global__ void __launch_bounds__(256) k_final(const float* __restrict__ be,
                                               const float* __restrict__ br,
                                               float* __restrict__ out) {
    __shared__ __align__(16) char sbuf[49152];
    __nv_bfloat16* As0 = (__nv_bfloat16*)sbuf;
    __nv_bfloat16* As1 = As0 + 8192;
    __nv_bfloat16* Bs0 = As1 + 8192;
    __nv_bfloat16* Bs1 = Bs0 + 4096;
    int t = threadIdx.x, lane = t & 31, wid = t >> 5;
    int wm = wid >> 1, wn = wid & 1;
    int row0 = blockIdx.x * 128, col0 = blockIdx.y * 64, dual = blockIdx.z;
    float accZ[2][4][4], accS[2][4][4];
#pragma unroll
    for (int a = 0; a < 2; a++)
#pragma unroll
        for (int bq = 0; bq < 4; bq++)
#pragma unroll
            for (int c = 0; c < 4; c++) { accZ[a][bq][c] = 0.f; accS[a][bq][c] = 0.f; }
    gemm_phase(accZ, g_ob[dual], 384, row0, Nn, g_gateT[dual], 384, col0, 384,
               As0, As1, Bs0, Bs1, t, wm, wn, lane);
    gemm_phase(accZ, g_SA3[dual], 192, row0, Nn, g_PGtn[dual], Pp, col0, 64,
               As0, As1, Bs0, Bs1, t, wm, wn, lane);
    gemm_phase(accS, g_SA3[dual], 192, row0, Nn, g_PB3[dual], 192, col0, 192,
               As0, As1, Bs0, Bs1, t, wm, wn, lane);
    const float* bias = dual ? br : be;
    // fp16 feature source for this 64-col tile (tile lies inside one 128-slice)
    const __half* fsl = (col0 < 128) ? g_fh0[dual] : (col0 < 256 ? g_fh1[dual] : g_fh2[dual]);
    int cbase = col0 & 127;
#pragma unroll
    for (int mt = 0; mt < 2; mt++)
#pragma unroll
        for (int n8 = 0; n8 < 4; n8++) {
            int rbase = wm * 32 + mt * 16 + (lane >> 2);
            int lc2 = wn * 32 + n8 * 8 + (lane & 3) * 2;
            int gc = col0 + lc2;
            float b0 = bias[gc], b1 = bias[gc + 1];
#pragma unroll
            for (int h = 0; h < 2; h++) {
                int gr = row0 + rbase + h * 8;
                if (gr < Nn) {
                    float z0 = accZ[mt][n8][h * 2], z1 = accZ[mt][n8][h * 2 + 1];
                    float s0 = accS[mt][n8][h * 2], s1 = accS[mt][n8][h * 2 + 1];
                    unsigned uov = *(const unsigned*)&fsl[(size_t)gr * Fd + cbase + lc2];
                    float2 ov = __half22float2(*(__half2*)&uov);
                    float gt0 = 1.f / (1.f + expf(-(z0 + b0)));
                    float gt1 = 1.f / (1.f + expf(-(z1 + b1)));
                    float o0 = ov.x - (1.f - gt0) * s0;
                    float o1 = ov.y - (1.f - gt1) * s1;
                    *(float2*)&out[(size_t)gr * 768 + dual * 384 + gc] = make_float2(o0, o1);
                }
            }
        }
}

// ---------------- launch ----------------
extern "C" void kernel_launch(void* const* d_in, const int* in_sizes, int n_in,
                              void* d_out, int out_size) {
    const float* ent = (const float*)d_in[0];
    const float* rel = (const float*)d_in[1];
    const int* esrc = (const int*)d_in[2];
    const int* edst = (const int*)d_in[3];
    const int* erel = (const int*)d_in[4];
    const float* attn_e = (const float*)d_in[5];
    const float* gate_e = (const float*)d_in[6];
    const float* proxy_e = (const float*)d_in[7];
    const float* bias_e = (const float*)d_in[8];
    const float* attn_r = (const float*)d_in[9];
    const float* gate_r = (const float*)d_in[10];
    const float* proxy_r = (const float*)d_in[11];
    const float* bias_r = (const float*)d_in[12];
    float* out = (float*)d_out;

    k_zero<<<(Nn + 255) / 256, 256>>>();
    k_count<<<(Ne + 255) / 256, 256>>>(edst);
    k_scan<<<1, 1024>>>();
    k_scatter<<<(Ne + 255) / 256, 256>>>(esrc, edst, erel);
    k_relnorm<<<Rr, 128>>>(rel, attn_e, attn_r);

    int convTot = (Nn + Rr) * Fd / 4;
    k_conv16<<<(convTot + 255) / 256, 256>>>(ent, rel);

    int wblocks = (Nn + 7) / 8;
    k_initstats<<<wblocks, 256>>>();
    k_agg<<<wblocks, 256>>>(0);
    k_agg<<<wblocks, 256>>>(1);

    k_prep_gate<<<dim3(FDh, 2), FDh>>>(gate_e, gate_r);
    k_prep_proxy<<<dim3(Pp, 2), FDh>>>(proxy_e, proxy_r);
    k_prep_pg<<<dim3(FDh, 2), Pp>>>(proxy_e, proxy_r, gate_e, gate_r);
    k_rnorm<<<dim3(wblocks, 2), 256>>>();

    int mblocks = (Nn + 127) / 128;
    k_S<<<dim3(mblocks, 1, 2), 256>>>();
    k_final<<<dim3(mblocks, 6, 2), 256>>>(bias_e, bias_r, out);
}